// round 1
// baseline (speedup 1.0000x reference)
#include <cuda_runtime.h>
#include <math.h>

// Problem constants
#define L_    2048
#define DM    1024
#define DI    2048
#define DS    16
#define NB    2
#define NTOK  (NB * L_)   // 4096 tokens
#define E2    (2 * DI)    // 4096 rows of xz

// ---------------- workspace (static device globals; no allocation) ----------
__device__ float g_xz[NB * E2 * L_];          // in_proj output  [b][e][l]
__device__ float g_xc[2][NB * DI * L_];       // conv+silu out   [br][b][d][t]
__device__ float g_xdbl[2][NB * 96 * L_];     // x_proj out      [br][b][r][t]
__device__ float g_delta[2][NB * DI * L_];    // softplus(dt)    [br][b][d][t]
__device__ float g_y[2][NB * DI * L_];        // branch outputs  [br][b][d][t]

__device__ __forceinline__ float softplus_f(float x) {
    return (x > 20.f) ? x : log1pf(__expf(x));
}

// ---------------------------------------------------------------------------
// Generic tiled fp32 GEMM, specialized by MODE for operand sourcing + epilogue
//   MODE 0: in_proj   C = W(4096x1024) * hs^T    -> g_xz[b][e][l]
//   MODE 3: x_proj    C = W(96x2048)   * xc      -> g_xdbl[br][b][r][t]
//   MODE 1: dt_proj   C = W(2048x64)   * dtr ;   softplus(+bias) -> g_delta
//   MODE 2: out_proj  C = W(1024x2048) * (y_f + flip(y_r)) -> d_out[b][l][m]
// A is always row-major [M][K] (K contiguous).
// ---------------------------------------------------------------------------
template<int MODE, int BM, int BN, int BK, int TM, int TN>
__global__ void __launch_bounds__((BM / TM) * (BN / TN))
gemm_k(const float* __restrict__ A, const float* __restrict__ Xn,
       const float* __restrict__ bias, float* __restrict__ Cout,
       int M, int K, int br)
{
    constexpr int NT  = (BM / TM) * (BN / TN);
    constexpr int BMP = BM + 1;
    constexpr int BNP = BN + 1;
    __shared__ float As[BK * BMP];
    __shared__ float Bs[BK * BNP];

    const int tid = threadIdx.x;
    const int n0  = blockIdx.x * BN;   // token tile origin
    const int m0  = blockIdx.y * BM;   // row tile origin
    const int bb  = n0 / L_;           // batch (tile never crosses batch: L_%BN==0)
    const int t0  = n0 - bb * L_;      // time within batch
    const int tx  = tid % (BN / TN);
    const int ty  = tid / (BN / TN);

    float acc[TM][TN];
    #pragma unroll
    for (int i = 0; i < TM; i++)
        #pragma unroll
        for (int j = 0; j < TN; j++) acc[i][j] = 0.f;

    for (int k0 = 0; k0 < K; k0 += BK) {
        // ---- load A tile (transposed into smem: As[k][m]) ----
        #pragma unroll
        for (int i = 0; i < (BM * BK) / NT; i++) {
            int idx = tid + i * NT;
            int m = idx / BK, kk = idx % BK;
            As[kk * BMP + m] = A[(m0 + m) * K + (k0 + kk)];
        }
        // ---- load B tile: Bs[k][n] ----
        #pragma unroll
        for (int i = 0; i < (BK * BN) / NT; i++) {
            int idx = tid + i * NT;
            if (MODE == 0) {
                int n = idx / BK, kk = idx % BK;          // hs: token-major, K contig
                Bs[kk * BNP + n] = Xn[(n0 + n) * K + (k0 + kk)];
            } else {
                int kk = idx / BN, n = idx % BN;          // [k][t] layout, t contig
                float v;
                if (MODE == 3) {
                    v = g_xc[br][(bb * DI + k0 + kk) * L_ + (t0 + n)];
                } else if (MODE == 1) {
                    v = g_xdbl[br][(bb * 96 + k0 + kk) * L_ + (t0 + n)];
                } else { // MODE 2: sum forward + time-flipped reverse branch
                    v = g_y[0][(bb * DI + k0 + kk) * L_ + (t0 + n)]
                      + g_y[1][(bb * DI + k0 + kk) * L_ + (L_ - 1 - (t0 + n))];
                }
                Bs[kk * BNP + n] = v;
            }
        }
        __syncthreads();

        // ---- compute ----
        #pragma unroll
        for (int kk = 0; kk < BK; kk++) {
            float ra[TM], rb[TN];
            #pragma unroll
            for (int i = 0; i < TM; i++) ra[i] = As[kk * BMP + ty * TM + i];
            #pragma unroll
            for (int j = 0; j < TN; j++) rb[j] = Bs[kk * BNP + tx * TN + j];
            #pragma unroll
            for (int i = 0; i < TM; i++)
                #pragma unroll
                for (int j = 0; j < TN; j++)
                    acc[i][j] = fmaf(ra[i], rb[j], acc[i][j]);
        }
        __syncthreads();
    }

    // ---- epilogue ----
    #pragma unroll
    for (int i = 0; i < TM; i++) {
        int m = m0 + ty * TM + i;
        #pragma unroll
        for (int j = 0; j < TN; j++) {
            int t = t0 + tx * TN + j;
            float v = acc[i][j];
            if (MODE == 0) {
                g_xz[(bb * E2 + m) * L_ + t] = v;
            } else if (MODE == 3) {
                g_xdbl[br][(bb * 96 + m) * L_ + t] = v;
            } else if (MODE == 1) {
                g_delta[br][(bb * DI + m) * L_ + t] = softplus_f(v + bias[m]);
            } else { // MODE 2: out[b][l][m]
                Cout[(bb * L_ + t) * DM + m] = v;
            }
        }
    }
}

// ---------------------------------------------------------------------------
// Causal depthwise conv (K=4) + bias + SiLU, with optional time reversal.
// Reads x-part of g_xz, writes g_xc[br] in scan-time order.
// ---------------------------------------------------------------------------
__global__ void conv_silu_k(const float* __restrict__ cw,
                            const float* __restrict__ cb, int br, int dir)
{
    int idx = blockIdx.x * blockDim.x + threadIdx.x;
    if (idx >= NB * DI * L_) return;
    int t = idx % L_;
    int d = (idx / L_) % DI;
    int b = idx / (L_ * DI);
    const float* xrow = &g_xz[(b * E2 + d) * L_];
    float acc = cb[d];
    #pragma unroll
    for (int k = 0; k < 4; k++) {
        int tau = t - 3 + k;
        if (tau >= 0) {
            int l = dir ? (L_ - 1 - tau) : tau;
            acc = fmaf(cw[d * 4 + k], xrow[l], acc);
        }
    }
    g_xc[br][idx] = acc / (1.f + __expf(-acc));  // silu
}

// ---------------------------------------------------------------------------
// Selective scan. One thread per (channel, state): 16 lanes cooperate on one
// channel, warp = 2 channels. Block = 256 threads = 16 channels, all same b.
// Per-chunk smem staging of delta/u/z (per-channel) and B/C (shared across d).
// ---------------------------------------------------------------------------
#define TCH 64
__global__ void __launch_bounds__(256)
scan_k(const float* __restrict__ A_log, const float* __restrict__ Dp,
       int br, int dir)
{
    __shared__ float sd[16][TCH], su[16][TCH], sz[16][TCH];
    __shared__ float sB[TCH][17], sC[TCH][17];   // pad 17 vs STS conflicts

    const int tid = threadIdx.x;
    const int g = tid >> 4;         // channel within block
    const int n = tid & 15;         // state index
    const int c = blockIdx.x * 16 + g;
    const int b = c / DI;
    const int d = c - b * DI;
    const int bB = (blockIdx.x * 16) / DI;  // batch for the whole block

    const float An = -__expf(A_log[d * DS + n]);
    const float Dd = Dp[d];
    float h = 0.f;
    float* yrow = &g_y[br][(b * DI + d) * L_];

    for (int t0 = 0; t0 < L_; t0 += TCH) {
        // stage delta / u / z : 16 channels x TCH, coalesced along t
        #pragma unroll
        for (int i = 0; i < (16 * TCH) / 256; i++) {
            int idx = tid + i * 256;
            int cl = idx / TCH, tt = idx % TCH;
            int cc = blockIdx.x * 16 + cl;
            int bb2 = cc / DI, dd = cc - bb2 * DI;
            sd[cl][tt] = g_delta[br][(bb2 * DI + dd) * L_ + t0 + tt];
            su[cl][tt] = g_xc[br][(bb2 * DI + dd) * L_ + t0 + tt];
            int lmap = dir ? (L_ - 1 - (t0 + tt)) : (t0 + tt);
            sz[cl][tt] = g_xz[(bb2 * E2 + DI + dd) * L_ + lmap];
        }
        // stage B / C : TCH x 16, coalesced along t per state row
        #pragma unroll
        for (int i = 0; i < (16 * TCH) / 256; i++) {
            int idx = tid + i * 256;
            int nn = idx / TCH, tt = idx % TCH;
            sB[tt][nn] = g_xdbl[br][(bB * 96 + 64 + nn) * L_ + t0 + tt];
            sC[tt][nn] = g_xdbl[br][(bB * 96 + 80 + nn) * L_ + t0 + tt];
        }
        __syncthreads();

        #pragma unroll 4
        for (int tt = 0; tt < TCH; tt++) {
            float dt = sd[g][tt];
            float u  = su[g][tt];
            float e  = __expf(dt * An);
            h = fmaf(h, e, (dt * u) * sB[tt][n]);     // h = e*h + dt*u*B_t[n]
            float p = h * sC[tt][n];                   // partial y
            p += __shfl_xor_sync(0xffffffffu, p, 8);
            p += __shfl_xor_sync(0xffffffffu, p, 4);
            p += __shfl_xor_sync(0xffffffffu, p, 2);
            p += __shfl_xor_sync(0xffffffffu, p, 1);
            if (n == 0) {
                float z = sz[g][tt];
                float gate = z / (1.f + __expf(-z));   // silu(z)
                yrow[t0 + tt] = (p + Dd * u) * gate;
            }
        }
        __syncthreads();
    }
}

// ---------------------------------------------------------------------------
extern "C" void kernel_launch(void* const* d_in, const int* in_sizes, int n_in,
                              void* d_out, int out_size)
{
    const float* hs        = (const float*)d_in[0];
    const float* in_proj_w = (const float*)d_in[1];
    const float* conv_w[2] = { (const float*)d_in[2], (const float*)d_in[9]  };
    const float* conv_b[2] = { (const float*)d_in[3], (const float*)d_in[10] };
    const float* xpw[2]    = { (const float*)d_in[4], (const float*)d_in[11] };
    const float* dtw[2]    = { (const float*)d_in[5], (const float*)d_in[12] };
    const float* dtb[2]    = { (const float*)d_in[6], (const float*)d_in[13] };
    const float* Alog[2]   = { (const float*)d_in[7], (const float*)d_in[14] };
    const float* Dp[2]     = { (const float*)d_in[8], (const float*)d_in[15] };
    const float* out_w     = (const float*)d_in[16];
    float* out = (float*)d_out;

    // 1) in_proj: xz[b][e][l]
    gemm_k<0, 128, 128, 8, 8, 8>
        <<<dim3(NTOK / 128, E2 / 128), 256>>>(in_proj_w, hs, nullptr, nullptr,
                                              E2, DM, 0);

    // 2) per-branch pipelines (br 0 = forward, br 1 = time-reversed)
    for (int br = 0; br < 2; br++) {
        conv_silu_k<<<(NB * DI * L_ + 255) / 256, 256>>>(conv_w[br], conv_b[br],
                                                          br, br);
        gemm_k<3, 32, 128, 16, 4, 4>
            <<<dim3(NTOK / 128, 96 / 32), 256>>>(xpw[br], nullptr, nullptr,
                                                 nullptr, 96, DI, br);
        gemm_k<1, 128, 128, 8, 8, 8>
            <<<dim3(NTOK / 128, DI / 128), 256>>>(dtw[br], nullptr, dtb[br],
                                                  nullptr, DI, 64, br);
        scan_k<<<(NB * DI) / 16, 256>>>(Alog[br], Dp[br], br, br);
    }

    // 3) out_proj over (y_f + flip(y_r))
    gemm_k<2, 128, 128, 8, 8, 8>
        <<<dim3(NTOK / 128, DM / 128), 256>>>(out_w, nullptr, nullptr, out,
                                              DM, DI, 0);
}

// round 8
// speedup vs baseline: 1.6879x; 1.6879x over previous
#include <cuda_runtime.h>
#include <cuda_bf16.h>
#include <math.h>
#include <stdint.h>

// Problem constants
#define L_    2048
#define DM    1024
#define DI    2048
#define DS    16
#define NB    2
#define NTOK  (NB * L_)   // 4096 tokens
#define E2    (2 * DI)    // 4096 rows of xz

// ---------------- fp32 workspaces (static device globals) -------------------
__device__ float g_xz[NB * E2 * L_];          // in_proj output  [b][e][l]
__device__ float g_xc[2][NB * DI * L_];       // conv+silu out   [br][b][d][t]
__device__ float g_xdbl[2][NB * 96 * L_];     // x_proj out      [br][b][r][t]
__device__ float g_delta[2][NB * DI * L_];    // softplus(dt)    [br][b][d][t]
__device__ float g_yt[2][NTOK * DI];          // branch out      [b*L+t][d] (flip applied)

// ---------------- bf16 hi/lo split workspaces (16B aligned via uint4) -------
__device__ uint4 g_wi_sp[2][E2 * DM / 8];     // in_proj_w  hi/lo   rows=e,   K=1024
__device__ uint4 g_hs_sp[2][NTOK * DM / 8];   // hidden     hi/lo   rows=tok, K=1024
__device__ uint4 g_wo_sp[2][DM * DI / 8];     // out_proj_w hi/lo   rows=m,   K=2048
__device__ uint4 g_ys_sp[2][NTOK * DI / 8];   // y_f+y_r    hi/lo   rows=tok, K=2048

__device__ __forceinline__ float softplus_f(float x) {
    return (x > 20.f) ? x : log1pf(__expf(x));
}

#define SW128(o) ((o) ^ (((o) >> 3) & 0x70))

__device__ __forceinline__ uint32_t smem_u32(const void* p) {
    return (uint32_t)__cvta_generic_to_shared(p);
}
__device__ __forceinline__ void cpasync16(uint32_t d, const void* s) {
    asm volatile("cp.async.cg.shared.global [%0], [%1], 16;" :: "r"(d), "l"(s));
}
__device__ __forceinline__ void ldsm4(uint32_t a, uint32_t& r0, uint32_t& r1,
                                      uint32_t& r2, uint32_t& r3) {
    asm volatile("ldmatrix.sync.aligned.m8n8.x4.shared.b16 {%0,%1,%2,%3}, [%4];"
                 : "=r"(r0), "=r"(r1), "=r"(r2), "=r"(r3) : "r"(a));
}
__device__ __forceinline__ void mma16816(float* c, const uint32_t* a, const uint32_t* b) {
    asm volatile("mma.sync.aligned.m16n8k16.row.col.f32.bf16.bf16.f32 "
                 "{%0,%1,%2,%3}, {%4,%5,%6,%7}, {%8,%9}, {%0,%1,%2,%3};"
                 : "+f"(c[0]), "+f"(c[1]), "+f"(c[2]), "+f"(c[3])
                 : "r"(a[0]), "r"(a[1]), "r"(a[2]), "r"(a[3]), "r"(b[0]), "r"(b[1]));
}

// ---------------------------------------------------------------------------
// Split-bf16 tensor GEMM via mma.sync (HMMA): C[M,N] = A[M,K] * B[N,K]^T fp32.
//   MODE 0: A = in_proj_w (rows e),   B = hs  (rows token)  -> g_xz[b][e][l]
//   MODE 2: A = ysum (rows token),    B = wo  (rows m)      -> out[b][l][m]
// CTA tile 128x128, 8 warps (4x2), warp tile 32x64, BK=64, double-buffered
// cp.async pipeline. C = Ah*Bh + Ah*Bl + Al*Bh (3-MMA split, err ~2^-16).
// SMEM stage: Ah|Al|Bh|Bl, 16KB each (128 rows x 128B SW128) = 64KB; 2 stages.
// ---------------------------------------------------------------------------
template<int MODE>
__global__ void __launch_bounds__(256)
tgemm(float* __restrict__ Cout, int K)
{
    extern __shared__ char smem[];
    const uint32_t sb = smem_u32(smem);
    const int tid = threadIdx.x, lane = tid & 31, wid = tid >> 5;
    const int warp_m = wid & 3;          // 4 warps along M (32 rows each)
    const int warp_n = wid >> 2;         // 2 warps along N (64 cols each)
    const int n0 = blockIdx.x * 128, m0 = blockIdx.y * 128;
    const int kdiv8 = K >> 3;
    const int NC = K >> 6;

    const uint4 *Ah, *Al, *Bh, *Bl;
    if (MODE == 0) { Ah = g_wi_sp[0]; Al = g_wi_sp[1]; Bh = g_hs_sp[0]; Bl = g_hs_sp[1]; }
    else           { Ah = g_ys_sp[0]; Al = g_ys_sp[1]; Bh = g_wo_sp[0]; Bl = g_wo_sp[1]; }

    float acc[2][8][4];
    #pragma unroll
    for (int i = 0; i < 2; i++)
        #pragma unroll
        for (int j = 0; j < 8; j++)
            #pragma unroll
            for (int q = 0; q < 4; q++) acc[i][j][q] = 0.f;

    // per-thread cp.async source/dest precompute: thread covers 4 rows r, col cc
    // stage load: 128 rows x 8 x 16B per tile, 4 tiles.
    #define LOAD_STAGE(c, s) do {                                               \
        const int k8_ = (c) << 3;                                               \
        const uint32_t sbase_ = sb + (s) * 65536;                               \
        _Pragma("unroll")                                                       \
        for (int j_ = 0; j_ < 4; j_++) {                                        \
            int i_ = tid + j_ * 256;                                            \
            int r_ = i_ >> 3, cc_ = i_ & 7;                                     \
            uint32_t d_ = sbase_ + SW128(r_ * 128 + cc_ * 16);                  \
            size_t ao_ = (size_t)(m0 + r_) * kdiv8 + k8_ + cc_;                 \
            size_t bo_ = (size_t)(n0 + r_) * kdiv8 + k8_ + cc_;                 \
            cpasync16(d_,          Ah + ao_);                                   \
            cpasync16(d_ + 16384,  Al + ao_);                                   \
            cpasync16(d_ + 32768,  Bh + bo_);                                   \
            cpasync16(d_ + 49152,  Bl + bo_);                                   \
        }                                                                       \
        asm volatile("cp.async.commit_group;" ::: "memory");                    \
    } while (0)

    LOAD_STAGE(0, 0);

    for (int c = 0; c < NC; c++) {
        const int s = c & 1;
        if (c + 1 < NC) {
            LOAD_STAGE(c + 1, s ^ 1);
            asm volatile("cp.async.wait_group 1;" ::: "memory");
        } else {
            asm volatile("cp.async.wait_group 0;" ::: "memory");
        }
        __syncthreads();

        const uint32_t ba = sb + s * 65536;
        #pragma unroll
        for (int kf = 0; kf < 4; kf++) {
            const uint32_t kb = kf * 32 + (lane >> 4) * 16;
            uint32_t a[2][2][4];             // [hl][mt][4]
            #pragma unroll
            for (int hl = 0; hl < 2; hl++)
                #pragma unroll
                for (int mt = 0; mt < 2; mt++) {
                    uint32_t ad = ba + hl * 16384 +
                        SW128((warp_m * 32 + mt * 16 + (lane & 15)) * 128 + kb);
                    ldsm4(ad, a[hl][mt][0], a[hl][mt][1], a[hl][mt][2], a[hl][mt][3]);
                }
            uint32_t b[2][8][2];             // [hl][nt][2]
            #pragma unroll
            for (int hl = 0; hl < 2; hl++)
                #pragma unroll
                for (int p = 0; p < 4; p++) {
                    uint32_t r0, r1, r2, r3;
                    uint32_t bd = ba + 32768 + hl * 16384 +
                        SW128((warp_n * 64 + p * 16 + (lane & 15)) * 128 + kb);
                    ldsm4(bd, r0, r1, r2, r3);
                    b[hl][2*p][0] = r0; b[hl][2*p][1] = r2;      // ntile even
                    b[hl][2*p+1][0] = r1; b[hl][2*p+1][1] = r3;  // ntile odd
                }
            #pragma unroll
            for (int mt = 0; mt < 2; mt++)
                #pragma unroll
                for (int nt = 0; nt < 8; nt++) {
                    mma16816(acc[mt][nt], a[0][mt], b[0][nt]);   // hi*hi
                    mma16816(acc[mt][nt], a[0][mt], b[1][nt]);   // hi*lo
                    mma16816(acc[mt][nt], a[1][mt], b[0][nt]);   // lo*hi
                }
        }
        __syncthreads();
    }

    // ---- epilogue: lane l holds (row = base + l/4 [+8], cols = (l%4)*2, +1) ----
    #pragma unroll
    for (int mt = 0; mt < 2; mt++) {
        int row = m0 + warp_m * 32 + mt * 16 + (lane >> 2);
        #pragma unroll
        for (int nt = 0; nt < 8; nt++) {
            int col = n0 + warp_n * 64 + nt * 8 + (lane & 3) * 2;
            float2 v01 = make_float2(acc[mt][nt][0], acc[mt][nt][1]);
            float2 v23 = make_float2(acc[mt][nt][2], acc[mt][nt][3]);
            if (MODE == 0) {
                int bb = col >> 11, t = col & 2047;     // col = token
                *(float2*)&g_xz[((size_t)(bb * E2 + row)) * L_ + t] = v01;
                *(float2*)&g_xz[((size_t)(bb * E2 + row + 8)) * L_ + t] = v23;
            } else {
                *(float2*)&Cout[(size_t)row * DM + col] = v01;        // row = token
                *(float2*)&Cout[(size_t)(row + 8) * DM + col] = v23;
            }
        }
    }
}

// ======================= bf16 split conversion ==============================
__device__ __forceinline__ void split4(float4 f, uint2& hv, uint2& lv) {
    __nv_bfloat16 h0 = __float2bfloat16_rn(f.x), h1 = __float2bfloat16_rn(f.y);
    __nv_bfloat16 h2 = __float2bfloat16_rn(f.z), h3 = __float2bfloat16_rn(f.w);
    __nv_bfloat16 l0 = __float2bfloat16_rn(f.x - __bfloat162float(h0));
    __nv_bfloat16 l1 = __float2bfloat16_rn(f.y - __bfloat162float(h1));
    __nv_bfloat16 l2 = __float2bfloat16_rn(f.z - __bfloat162float(h2));
    __nv_bfloat16 l3 = __float2bfloat16_rn(f.w - __bfloat162float(h3));
    hv.x = ((uint32_t)__bfloat16_as_ushort(h1) << 16) | __bfloat16_as_ushort(h0);
    hv.y = ((uint32_t)__bfloat16_as_ushort(h3) << 16) | __bfloat16_as_ushort(h2);
    lv.x = ((uint32_t)__bfloat16_as_ushort(l1) << 16) | __bfloat16_as_ushort(l0);
    lv.y = ((uint32_t)__bfloat16_as_ushort(l3) << 16) | __bfloat16_as_ushort(l2);
}

__global__ void split_sel_k(const float* __restrict__ src, int which, int n4) {
    int i = blockIdx.x * blockDim.x + threadIdx.x;
    if (i >= n4) return;
    uint2 *hi, *lo;
    if (which == 0)      { hi = (uint2*)g_wi_sp[0]; lo = (uint2*)g_wi_sp[1]; }
    else if (which == 1) { hi = (uint2*)g_hs_sp[0]; lo = (uint2*)g_hs_sp[1]; }
    else                 { hi = (uint2*)g_wo_sp[0]; lo = (uint2*)g_wo_sp[1]; }
    float4 f = ((const float4*)src)[i];
    uint2 hv, lv; split4(f, hv, lv);
    hi[i] = hv; lo[i] = lv;
}

__global__ void ysum_split_k() {
    int i = blockIdx.x * blockDim.x + threadIdx.x;
    if (i >= NTOK * DI / 4) return;
    float4 a = ((const float4*)g_yt[0])[i];
    float4 b = ((const float4*)g_yt[1])[i];
    float4 s = make_float4(a.x + b.x, a.y + b.y, a.z + b.z, a.w + b.w);
    uint2 hv, lv; split4(s, hv, lv);
    ((uint2*)g_ys_sp[0])[i] = hv;
    ((uint2*)g_ys_sp[1])[i] = lv;
}

// ---------------------------------------------------------------------------
// SIMT GEMM for the small projections:
//   MODE 3: x_proj    C = W(96x2048)   * xc      -> g_xdbl[br][b][r][t]
//   MODE 1: dt_proj   C = W(2048x64)   * dtr ;   softplus(+bias) -> g_delta
// ---------------------------------------------------------------------------
template<int MODE, int BM, int BN, int BK, int TM, int TN>
__global__ void __launch_bounds__((BM / TM) * (BN / TN))
gemm_k(const float* __restrict__ A, const float* __restrict__ bias,
       int M, int K, int br)
{
    constexpr int NT  = (BM / TM) * (BN / TN);
    constexpr int BMP = BM + 1;
    constexpr int BNP = BN + 1;
    __shared__ float As[BK * BMP];
    __shared__ float Bs[BK * BNP];

    const int tid = threadIdx.x;
    const int n0  = blockIdx.x * BN;
    const int m0  = blockIdx.y * BM;
    const int bb  = n0 / L_;
    const int t0  = n0 - bb * L_;
    const int tx  = tid % (BN / TN);
    const int ty  = tid / (BN / TN);

    float acc[TM][TN];
    #pragma unroll
    for (int i = 0; i < TM; i++)
        #pragma unroll
        for (int j = 0; j < TN; j++) acc[i][j] = 0.f;

    for (int k0 = 0; k0 < K; k0 += BK) {
        #pragma unroll
        for (int i = 0; i < (BM * BK) / NT; i++) {
            int idx = tid + i * NT;
            int m = idx / BK, kk = idx % BK;
            As[kk * BMP + m] = A[(m0 + m) * K + (k0 + kk)];
        }
        #pragma unroll
        for (int i = 0; i < (BK * BN) / NT; i++) {
            int idx = tid + i * NT;
            int kk = idx / BN, n = idx % BN;
            float v;
            if (MODE == 3)
                v = g_xc[br][(bb * DI + k0 + kk) * L_ + (t0 + n)];
            else
                v = g_xdbl[br][(bb * 96 + k0 + kk) * L_ + (t0 + n)];
            Bs[kk * BNP + n] = v;
        }
        __syncthreads();

        #pragma unroll
        for (int kk = 0; kk < BK; kk++) {
            float ra[TM], rb[TN];
            #pragma unroll
            for (int i = 0; i < TM; i++) ra[i] = As[kk * BMP + ty * TM + i];
            #pragma unroll
            for (int j = 0; j < TN; j++) rb[j] = Bs[kk * BNP + tx * TN + j];
            #pragma unroll
            for (int i = 0; i < TM; i++)
                #pragma unroll
                for (int j = 0; j < TN; j++)
                    acc[i][j] = fmaf(ra[i], rb[j], acc[i][j]);
        }
        __syncthreads();
    }

    #pragma unroll
    for (int i = 0; i < TM; i++) {
        int m = m0 + ty * TM + i;
        #pragma unroll
        for (int j = 0; j < TN; j++) {
            int t = t0 + tx * TN + j;
            float v = acc[i][j];
            if (MODE == 3)
                g_xdbl[br][(bb * 96 + m) * L_ + t] = v;
            else
                g_delta[br][(bb * DI + m) * L_ + t] = softplus_f(v + bias[m]);
        }
    }
}

// ---------------------------------------------------------------------------
// Causal depthwise conv (K=4) + bias + SiLU, optional time reversal.
// ---------------------------------------------------------------------------
__global__ void conv_silu_k(const float* __restrict__ cw,
                            const float* __restrict__ cb, int br, int dir)
{
    int idx = blockIdx.x * blockDim.x + threadIdx.x;
    if (idx >= NB * DI * L_) return;
    int t = idx % L_;
    int d = (idx / L_) % DI;
    int b = idx / (L_ * DI);
    const float* xrow = &g_xz[(b * E2 + d) * L_];
    float acc = cb[d];
    #pragma unroll
    for (int k = 0; k < 4; k++) {
        int tau = t - 3 + k;
        if (tau >= 0) {
            int l = dir ? (L_ - 1 - tau) : tau;
            acc = fmaf(cw[d * 4 + k], xrow[l], acc);
        }
    }
    g_xc[br][idx] = acc / (1.f + __expf(-acc));
}

// ---------------------------------------------------------------------------
// Selective scan; writes y to [b*L + t][d] layout with time flip applied.
// ---------------------------------------------------------------------------
#define TCH 64
__global__ void __launch_bounds__(256)
scan_k(const float* __restrict__ A_log, const float* __restrict__ Dp,
       int br, int dir)
{
    __shared__ float sd[16][TCH], su[16][TCH], sz[16][TCH];
    __shared__ float sB[TCH][17], sC[TCH][17];

    const int tid = threadIdx.x;
    const int g = tid >> 4;
    const int n = tid & 15;
    const int c = blockIdx.x * 16 + g;
    const int b = c / DI;
    const int d = c - b * DI;
    const int bB = (blockIdx.x * 16) / DI;

    const float An = -__expf(A_log[d * DS + n]);
    const float Dd = Dp[d];
    float h = 0.f;

    for (int t0 = 0; t0 < L_; t0 += TCH) {
        #pragma unroll
        for (int i = 0; i < (16 * TCH) / 256; i++) {
            int idx = tid + i * 256;
            int cl = idx / TCH, tt = idx % TCH;
            int cc = blockIdx.x * 16 + cl;
            int bb2 = cc / DI, dd = cc - bb2 * DI;
            sd[cl][tt] = g_delta[br][(bb2 * DI + dd) * L_ + t0 + tt];
            su[cl][tt] = g_xc[br][(bb2 * DI + dd) * L_ + t0 + tt];
            int lmap = dir ? (L_ - 1 - (t0 + tt)) : (t0 + tt);
            sz[cl][tt] = g_xz[(bb2 * E2 + DI + dd) * L_ + lmap];
        }
        #pragma unroll
        for (int i = 0; i < (16 * TCH) / 256; i++) {
            int idx = tid + i * 256;
            int nn = idx / TCH, tt = idx % TCH;
            sB[tt][nn] = g_xdbl[br][(bB * 96 + 64 + nn) * L_ + t0 + tt];
            sC[tt][nn] = g_xdbl[br][(bB * 96 + 80 + nn) * L_ + t0 + tt];
        }
        __syncthreads();

        #pragma unroll 4
        for (int tt = 0; tt < TCH; tt++) {
            float dt = sd[g][tt];
            float u  = su[g][tt];
            float e  = __expf(dt * An);
            h = fmaf(h, e, (dt * u) * sB[tt][n]);
            float p = h * sC[tt][n];
            p += __shfl_xor_sync(0xffffffffu, p, 8);
            p += __shfl_xor_sync(0xffffffffu, p, 4);
            p += __shfl_xor_sync(0xffffffffu, p, 2);
            p += __shfl_xor_sync(0xffffffffu, p, 1);
            if (n == 0) {
                float z = sz[g][tt];
                float gate = z / (1.f + __expf(-z));
                int tmap = dir ? (L_ - 1 - (t0 + tt)) : (t0 + tt);
                g_yt[br][((size_t)b * L_ + tmap) * DI + d] = (p + Dd * u) * gate;
            }
        }
        __syncthreads();
    }
}

// ---------------------------------------------------------------------------
extern "C" void kernel_launch(void* const* d_in, const int* in_sizes, int n_in,
                              void* d_out, int out_size)
{
    const float* hs        = (const float*)d_in[0];
    const float* in_proj_w = (const float*)d_in[1];
    const float* conv_w[2] = { (const float*)d_in[2], (const float*)d_in[9]  };
    const float* conv_b[2] = { (const float*)d_in[3], (const float*)d_in[10] };
    const float* xpw[2]    = { (const float*)d_in[4], (const float*)d_in[11] };
    const float* dtw[2]    = { (const float*)d_in[5], (const float*)d_in[12] };
    const float* dtb[2]    = { (const float*)d_in[6], (const float*)d_in[13] };
    const float* Alog[2]   = { (const float*)d_in[7], (const float*)d_in[14] };
    const float* Dp[2]     = { (const float*)d_in[8], (const float*)d_in[15] };
    const float* out_w     = (const float*)d_in[16];
    float* out = (float*)d_out;

    constexpr int SMEMSZ = 2 * 65536;   // 128KB, 2 stages x (4 x 16KB tiles)
    cudaFuncSetAttribute(tgemm<0>, cudaFuncAttributeMaxDynamicSharedMemorySize, SMEMSZ);
    cudaFuncSetAttribute(tgemm<2>, cudaFuncAttributeMaxDynamicSharedMemorySize, SMEMSZ);

    // 0) split weights + input to bf16 hi/lo
    split_sel_k<<<(E2 * DM / 4) / 256, 256>>>(in_proj_w, 0, E2 * DM / 4);
    split_sel_k<<<(NTOK * DM / 4) / 256, 256>>>(hs, 1, NTOK * DM / 4);
    split_sel_k<<<(DM * DI / 4) / 256, 256>>>(out_w, 2, DM * DI / 4);

    // 1) in_proj on tensor cores (HMMA): xz[b][e][l]
    tgemm<0><<<dim3(NTOK / 128, E2 / 128), 256, SMEMSZ>>>(nullptr, DM);

    // 2) per-branch pipelines (br 0 = forward, br 1 = time-reversed)
    for (int br = 0; br < 2; br++) {
        conv_silu_k<<<(NB * DI * L_ + 255) / 256, 256>>>(conv_w[br], conv_b[br], br, br);
        gemm_k<3, 32, 128, 16, 4, 4>
            <<<dim3(NTOK / 128, 96 / 32), 256>>>(xpw[br], nullptr, 96, DI, br);
        gemm_k<1, 128, 128, 8, 8, 8>
            <<<dim3(NTOK / 128, DI / 128), 256>>>(dtw[br], dtb[br], DI, 64, br);
        scan_k<<<(NB * DI) / 16, 256>>>(Alog[br], Dp[br], br, br);
    }

    // 3) sum branches + split, out_proj on tensor cores (token-major M side)
    ysum_split_k<<<(NTOK * DI / 4) / 256, 256>>>();
    tgemm<2><<<dim3(DM / 128, NTOK / 128), 256, SMEMSZ>>>(out, DI);
}